// round 14
// baseline (speedup 1.0000x reference)
#include <cuda_runtime.h>
#include <cuda_bf16.h>
#include <cstdint>

// Problem dims (fixed)
#define BB 2
#define SS 2048
#define DD 2048
#define HH 32
#define KVH 8
#define HD 64
#define MTOT (BB*SS)  // 4096

// ---------------- scratch ----------------
__device__ float g_q[(size_t)BB*SS*HH*HD];   // [b,s,h,d]  32MB
__device__ float g_k[(size_t)BB*SS*KVH*HD];  // 8MB
__device__ float g_v[(size_t)BB*SS*KVH*HD];  // 8MB
__device__ float g_o[(size_t)BB*SS*HH*HD];   // 32MB

__device__ __forceinline__ uint32_t f2tf32(float f) {
    uint32_t r; asm("cvt.rna.tf32.f32 %0, %1;" : "=r"(r) : "f"(f)); return r;
}

__device__ __forceinline__ void mma_tf32_16x8x8(
    float& d0, float& d1, float& d2, float& d3,
    uint32_t a0, uint32_t a1, uint32_t a2, uint32_t a3,
    uint32_t b0, uint32_t b1)
{
    asm volatile(
        "mma.sync.aligned.m16n8k8.row.col.f32.tf32.tf32.f32 "
        "{%0,%1,%2,%3}, {%4,%5,%6,%7}, {%8,%9}, {%0,%1,%2,%3};"
        : "+f"(d0), "+f"(d1), "+f"(d2), "+f"(d3)
        : "r"(a0), "r"(a1), "r"(a2), "r"(a3), "r"(b0), "r"(b1));
}

// ---------------- mma.sync tf32 GEMM: C[M,N] = A[M,K] @ B[N,K]^T ----------------
// CTA tile 128x128, 256 threads, warp tile 32x64, K-chunk 32.
// Double-buffered smem (ping/pong), register-staged global loads, 1 sync/chunk.
#define GBK 32
#define GPAD 36
#define GT (128 * GPAD)
#define SMEM_GEMM (4 * GT * 4)   // 73728 bytes

__global__ __launch_bounds__(256) void gemm_mma(
    const float* __restrict__ A, const float* __restrict__ B,
    float* __restrict__ C, int M, int N, int K)
{
    extern __shared__ uint32_t smd[];

    const int tid  = threadIdx.x;
    const int warp = tid >> 5;
    const int lane = tid & 31;
    const int wm = (warp & 3) * 32;
    const int wn = (warp >> 2) * 64;
    const int m0 = blockIdx.y * 128;
    const int n0 = blockIdx.x * 128;

    const int lrow = tid >> 1;
    const int lcol = (tid & 1) * 16;

    const int ar = lane >> 2;
    const int ac = lane & 3;

    float acc[2][8][4];
    #pragma unroll
    for (int i = 0; i < 2; i++)
        #pragma unroll
        for (int j = 0; j < 8; j++)
            #pragma unroll
            for (int l = 0; l < 4; l++) acc[i][j][l] = 0.0f;

    const float* Ap = A + (size_t)(m0 + lrow) * K + lcol;
    const float* Bp = B + (size_t)(n0 + lrow) * K + lcol;

    float4 ra[4], rb[4];
    // preload chunk 0
    #pragma unroll
    for (int i = 0; i < 4; i++) {
        ra[i] = *(const float4*)(Ap + i * 4);
        rb[i] = *(const float4*)(Bp + i * 4);
    }
    {
        uint32_t* da = &smd[lrow * GPAD + lcol];
        uint32_t* db = &smd[GT + lrow * GPAD + lcol];
        #pragma unroll
        for (int i = 0; i < 4; i++) {
            da[i*4+0] = f2tf32(ra[i].x); da[i*4+1] = f2tf32(ra[i].y);
            da[i*4+2] = f2tf32(ra[i].z); da[i*4+3] = f2tf32(ra[i].w);
            db[i*4+0] = f2tf32(rb[i].x); db[i*4+1] = f2tf32(rb[i].y);
            db[i*4+2] = f2tf32(rb[i].z); db[i*4+3] = f2tf32(rb[i].w);
        }
    }
    __syncthreads();

    const int NC = K / GBK;
    for (int c = 0; c < NC; c++) {
        // 1) issue global loads for next chunk (latency hides under compute)
        if (c + 1 < NC) {
            const int kn = (c + 1) * GBK;
            #pragma unroll
            for (int i = 0; i < 4; i++) {
                ra[i] = *(const float4*)(Ap + kn + i * 4);
                rb[i] = *(const float4*)(Bp + kn + i * 4);
            }
        }

        // 2) compute on current buffer
        uint32_t* As_ = &smd[(c & 1) * 2 * GT];
        uint32_t* Bs_ = As_ + GT;
        #pragma unroll
        for (int ks = 0; ks < 4; ks++) {
            const int kk = ks * 8;
            uint32_t af[2][4];
            #pragma unroll
            for (int mi = 0; mi < 2; mi++) {
                const uint32_t* base = &As_[(wm + mi * 16 + ar) * GPAD + kk + ac];
                af[mi][0] = base[0];
                af[mi][1] = base[8 * GPAD];
                af[mi][2] = base[4];
                af[mi][3] = base[8 * GPAD + 4];
            }
            uint32_t bf[8][2];
            #pragma unroll
            for (int ni = 0; ni < 8; ni++) {
                const uint32_t* base = &Bs_[(wn + ni * 8 + ar) * GPAD + kk + ac];
                bf[ni][0] = base[0];
                bf[ni][1] = base[4];
            }
            #pragma unroll
            for (int mi = 0; mi < 2; mi++)
                #pragma unroll
                for (int ni = 0; ni < 8; ni++)
                    mma_tf32_16x8x8(acc[mi][ni][0], acc[mi][ni][1],
                                    acc[mi][ni][2], acc[mi][ni][3],
                                    af[mi][0], af[mi][1], af[mi][2], af[mi][3],
                                    bf[ni][0], bf[ni][1]);
        }

        // 3) stage next chunk into the other buffer
        if (c + 1 < NC) {
            uint32_t* da = &smd[((c + 1) & 1) * 2 * GT + lrow * GPAD + lcol];
            uint32_t* db = da + GT;
            #pragma unroll
            for (int i = 0; i < 4; i++) {
                da[i*4+0] = f2tf32(ra[i].x); da[i*4+1] = f2tf32(ra[i].y);
                da[i*4+2] = f2tf32(ra[i].z); da[i*4+3] = f2tf32(ra[i].w);
                db[i*4+0] = f2tf32(rb[i].x); db[i*4+1] = f2tf32(rb[i].y);
                db[i*4+2] = f2tf32(rb[i].z); db[i*4+3] = f2tf32(rb[i].w);
            }
        }
        __syncthreads();
    }

    const int cr = lane >> 2;
    const int cc = (lane & 3) * 2;
    #pragma unroll
    for (int mi = 0; mi < 2; mi++) {
        #pragma unroll
        for (int ni = 0; ni < 8; ni++) {
            size_t row = (size_t)(m0 + wm + mi * 16 + cr);
            int col = n0 + wn + ni * 8 + cc;
            *(float2*)&C[row * N + col] =
                make_float2(acc[mi][ni][0], acc[mi][ni][1]);
            *(float2*)&C[(row + 8) * N + col] =
                make_float2(acc[mi][ni][2], acc[mi][ni][3]);
        }
    }
}

// ---------------- RoPE (in-place, interleaved pairs) ----------------
__global__ void rope_kernel(float* __restrict__ buf,
                            const float* __restrict__ fc,
                            const float* __restrict__ fs,
                            int nh, int total)
{
    int idx = blockIdx.x * blockDim.x + threadIdx.x;
    if (idx >= total) return;
    int j = idx & 31;
    int t = idx >> 5;
    int s = (t / nh) % SS;
    float* p = buf + (size_t)t * HD + 2 * j;
    float2 v = *(float2*)p;
    float c = fc[s * 32 + j];
    float sn = fs[s * 32 + j];
    float2 r;
    r.x = v.x * c - v.y * sn;
    r.y = v.x * sn + v.y * c;
    *(float2*)p = r;
}

// ---------------- Flash attention on mma.sync tf32 ----------------
#define NEG_BIG (-1e30f)
#define QPAD 68
#define VPAD 36

__global__ __launch_bounds__(128) void attn_mma(
    const float* __restrict__ Qb, const float* __restrict__ Kb,
    const float* __restrict__ Vb, const int* __restrict__ amask,
    float* __restrict__ Ob)
{
    __shared__ uint32_t Qs[64][QPAD];
    __shared__ uint32_t Ks[32][QPAD];
    __shared__ uint32_t Vs[64][VPAD];
    __shared__ uint32_t Ps[64][VPAD];
    __shared__ float Ms[32];

    const int tid  = threadIdx.x;
    const int warp = tid >> 5;
    const int lane = tid & 31;
    const int ar = lane >> 2;
    const int ac = lane & 3;
    const int wq = warp * 16;

    const int q0 = blockIdx.x * 64;
    const int h  = blockIdx.y;
    const int b  = blockIdx.z;
    const int kvh = h >> 2;
    const float scale = 0.125f;

    {
        int row = tid >> 1;
        int c0  = (tid & 1) * 32;
        const float* qp = Qb + (((size_t)b * SS + q0 + row) * HH + h) * HD + c0;
        #pragma unroll
        for (int i = 0; i < 8; i++) {
            float4 v = *(const float4*)(qp + i * 4);
            uint32_t* d = &Qs[row][c0 + i * 4];
            d[0] = f2tf32(v.x * scale); d[1] = f2tf32(v.y * scale);
            d[2] = f2tf32(v.z * scale); d[3] = f2tf32(v.w * scale);
        }
    }

    float m_lo = NEG_BIG, m_hi = NEG_BIG, l_lo = 0.0f, l_hi = 0.0f;
    float o[8][4];
    #pragma unroll
    for (int i = 0; i < 8; i++)
        #pragma unroll
        for (int j = 0; j < 4; j++) o[i][j] = 0.0f;

    const int nkt = (q0 + 64) / 32;

    for (int kt = 0; kt < nkt; kt++) {
        const int k0 = kt * 32;
        {
            int row = tid >> 2;
            int c0  = (tid & 3) * 16;
            const float* kp = Kb + (((size_t)b * SS + k0 + row) * KVH + kvh) * HD + c0;
            const float* vp = Vb + (((size_t)b * SS + k0 + row) * KVH + kvh) * HD + c0;
            #pragma unroll
            for (int i = 0; i < 4; i++) {
                float4 v = *(const float4*)(kp + i * 4);
                uint32_t* d = &Ks[row][c0 + i * 4];
                d[0] = f2tf32(v.x); d[1] = f2tf32(v.y);
                d[2] = f2tf32(v.z); d[3] = f2tf32(v.w);
                float4 w = *(const float4*)(vp + i * 4);
                Vs[c0 + i * 4 + 0][row] = f2tf32(w.x);
                Vs[c0 + i * 4 + 1][row] = f2tf32(w.y);
                Vs[c0 + i * 4 + 2][row] = f2tf32(w.z);
                Vs[c0 + i * 4 + 3][row] = f2tf32(w.w);
            }
        }
        if (tid < 32) Ms[tid] = amask[b * SS + k0 + tid] ? 0.0f : NEG_BIG;
        __syncthreads();

        float s[4][4];
        #pragma unroll
        for (int i = 0; i < 4; i++)
            #pragma unroll
            for (int j = 0; j < 4; j++) s[i][j] = 0.0f;

        #pragma unroll
        for (int ks = 0; ks < 8; ks++) {
            const int kk = ks * 8;
            uint32_t a0 = Qs[wq + ar][kk + ac];
            uint32_t a1 = Qs[wq + ar + 8][kk + ac];
            uint32_t a2 = Qs[wq + ar][kk + ac + 4];
            uint32_t a3 = Qs[wq + ar + 8][kk + ac + 4];
            #pragma unroll
            for (int ni = 0; ni < 4; ni++) {
                uint32_t b0 = Ks[ni * 8 + ar][kk + ac];
                uint32_t b1 = Ks[ni * 8 + ar][kk + ac + 4];
                mma_tf32_16x8x8(s[ni][0], s[ni][1], s[ni][2], s[ni][3],
                                a0, a1, a2, a3, b0, b1);
            }
        }

        const int rg_lo = q0 + wq + ar;
        const int rg_hi = rg_lo + 8;
        float rmax_lo = NEG_BIG, rmax_hi = NEG_BIG;
        #pragma unroll
        for (int ni = 0; ni < 4; ni++) {
            int cl = ni * 8 + 2 * ac;
            int cg = k0 + cl;
            float mk0 = Ms[cl], mk1 = Ms[cl + 1];
            s[ni][0] += mk0; if (cg     > rg_lo) s[ni][0] = NEG_BIG;
            s[ni][1] += mk1; if (cg + 1 > rg_lo) s[ni][1] = NEG_BIG;
            s[ni][2] += mk0; if (cg     > rg_hi) s[ni][2] = NEG_BIG;
            s[ni][3] += mk1; if (cg + 1 > rg_hi) s[ni][3] = NEG_BIG;
            rmax_lo = fmaxf(rmax_lo, fmaxf(s[ni][0], s[ni][1]));
            rmax_hi = fmaxf(rmax_hi, fmaxf(s[ni][2], s[ni][3]));
        }
        rmax_lo = fmaxf(rmax_lo, __shfl_xor_sync(0xffffffffu, rmax_lo, 1));
        rmax_lo = fmaxf(rmax_lo, __shfl_xor_sync(0xffffffffu, rmax_lo, 2));
        rmax_hi = fmaxf(rmax_hi, __shfl_xor_sync(0xffffffffu, rmax_hi, 1));
        rmax_hi = fmaxf(rmax_hi, __shfl_xor_sync(0xffffffffu, rmax_hi, 2));

        float mn_lo = fmaxf(m_lo, rmax_lo);
        float mn_hi = fmaxf(m_hi, rmax_hi);
        float corr_lo = __expf(m_lo - mn_lo);
        float corr_hi = __expf(m_hi - mn_hi);
        m_lo = mn_lo; m_hi = mn_hi;

        float rsum_lo = 0.0f, rsum_hi = 0.0f;
        #pragma unroll
        for (int ni = 0; ni < 4; ni++) {
            int cl = ni * 8 + 2 * ac;
            float p0 = __expf(s[ni][0] - mn_lo);
            float p1 = __expf(s[ni][1] - mn_lo);
            float p2 = __expf(s[ni][2] - mn_hi);
            float p3 = __expf(s[ni][3] - mn_hi);
            rsum_lo += p0 + p1;
            rsum_hi += p2 + p3;
            Ps[wq + ar][cl]         = f2tf32(p0);
            Ps[wq + ar][cl + 1]     = f2tf32(p1);
            Ps[wq + ar + 8][cl]     = f2tf32(p2);
            Ps[wq + ar + 8][cl + 1] = f2tf32(p3);
        }
        rsum_lo += __shfl_xor_sync(0xffffffffu, rsum_lo, 1);
        rsum_lo += __shfl_xor_sync(0xffffffffu, rsum_lo, 2);
        rsum_hi += __shfl_xor_sync(0xffffffffu, rsum_hi, 1);
        rsum_hi += __shfl_xor_sync(0xffffffffu, rsum_hi, 2);
        l_lo = l_lo * corr_lo + rsum_lo;
        l_hi = l_hi * corr_hi + rsum_hi;

        #pragma unroll
        for (int ni = 0; ni < 8; ni++) {
            o[ni][0] *= corr_lo; o[ni][1] *= corr_lo;
            o[ni][2] *= corr_hi; o[ni][3] *= corr_hi;
        }
        __syncwarp();

        #pragma unroll
        for (int ks = 0; ks < 4; ks++) {
            const int kk = ks * 8;
            uint32_t a0 = Ps[wq + ar][kk + ac];
            uint32_t a1 = Ps[wq + ar + 8][kk + ac];
            uint32_t a2 = Ps[wq + ar][kk + ac + 4];
            uint32_t a3 = Ps[wq + ar + 8][kk + ac + 4];
            #pragma unroll
            for (int ni = 0; ni < 8; ni++) {
                uint32_t b0 = Vs[ni * 8 + ar][kk + ac];
                uint32_t b1 = Vs[ni * 8 + ar][kk + ac + 4];
                mma_tf32_16x8x8(o[ni][0], o[ni][1], o[ni][2], o[ni][3],
                                a0, a1, a2, a3, b0, b1);
            }
        }
        __syncthreads();
    }

    const float inv_lo = 1.0f / l_lo;
    const float inv_hi = 1.0f / l_hi;
    const int row_lo = q0 + wq + ar;
    #pragma unroll
    for (int ni = 0; ni < 8; ni++) {
        int d = ni * 8 + 2 * ac;
        *(float2*)&Ob[(((size_t)b * SS + row_lo) * HH + h) * HD + d] =
            make_float2(o[ni][0] * inv_lo, o[ni][1] * inv_lo);
        *(float2*)&Ob[(((size_t)b * SS + row_lo + 8) * HH + h) * HD + d] =
            make_float2(o[ni][2] * inv_hi, o[ni][3] * inv_hi);
    }
}

// ---------------- launch ----------------
extern "C" void kernel_launch(void* const* d_in, const int* in_sizes, int n_in,
                              void* d_out, int out_size)
{
    const float* x  = (const float*)d_in[0];
    const float* fc = (const float*)d_in[1];
    const float* fs = (const float*)d_in[2];
    const float* wq = (const float*)d_in[3];
    const float* wk = (const float*)d_in[4];
    const float* wv = (const float*)d_in[5];
    const float* wo = (const float*)d_in[6];
    const int*   am = (const int*)d_in[7];
    float* out = (float*)d_out;

    float *pq, *pk, *pv, *po;
    cudaGetSymbolAddress((void**)&pq, g_q);
    cudaGetSymbolAddress((void**)&pk, g_k);
    cudaGetSymbolAddress((void**)&pv, g_v);
    cudaGetSymbolAddress((void**)&po, g_o);

    cudaFuncSetAttribute(gemm_mma, cudaFuncAttributeMaxDynamicSharedMemorySize, SMEM_GEMM);

    // QKV projections on tensor cores (tf32 mma.sync, double-buffered)
    gemm_mma<<<dim3(DD / 128, MTOT / 128), 256, SMEM_GEMM>>>(x, wq, pq, MTOT, DD, DD);
    gemm_mma<<<dim3((KVH * HD) / 128, MTOT / 128), 256, SMEM_GEMM>>>(x, wk, pk, MTOT, KVH * HD, DD);
    gemm_mma<<<dim3((KVH * HD) / 128, MTOT / 128), 256, SMEM_GEMM>>>(x, wv, pv, MTOT, KVH * HD, DD);

    // RoPE on Q and K
    {
        int totq = BB * SS * HH * 32;
        int totk = BB * SS * KVH * 32;
        rope_kernel<<<(totq + 255) / 256, 256>>>(pq, fc, fs, HH, totq);
        rope_kernel<<<(totk + 255) / 256, 256>>>(pk, fc, fs, KVH, totk);
    }

    // attention on tensor cores (tf32 mma.sync flash)
    attn_mma<<<dim3(SS / 64, HH, BB), 128>>>(pq, pk, pv, am, po);

    // output projection on tensor cores
    gemm_mma<<<dim3(DD / 128, MTOT / 128), 256, SMEM_GEMM>>>(po, wo, out, MTOT, DD, DD);
}